// round 1
// baseline (speedup 1.0000x reference)
#include <cuda_runtime.h>

#define QDIM 128

__global__ void qop_kernel(const float* __restrict__ sr,
                           const float* __restrict__ si,
                           const float* __restrict__ params,
                           float* __restrict__ out,
                           int n_rows) {
    __shared__ float sp[QDIM];
    __shared__ float sd[QDIM];
    int tid = threadIdx.x;
    if (tid < QDIM) {
        float p = params[tid];
        sp[tid] = p;
        sd[tid] = 1.0f / (1.0f + expf(-p)) - p * p;   // sigmoid(p) - p^2
    }
    __syncthreads();

    int lane = tid & 31;
    // Each lane owns 4 consecutive columns for the whole kernel — hoist to regs.
    float4 p4 = *reinterpret_cast<const float4*>(sp + lane * 4);
    float4 d4 = *reinterpret_cast<const float4*>(sd + lane * 4);

    long long N = (long long)n_rows * QDIM;   // elements per output tensor
    int warps_per_block = blockDim.x >> 5;
    long long w  = (long long)blockIdx.x * warps_per_block + (tid >> 5);
    long long nw = (long long)gridDim.x * warps_per_block;

    for (long long row = w; row < (long long)n_rows; row += nw) {
        const float4* pr = reinterpret_cast<const float4*>(sr + row * QDIM) + lane;
        const float4* pi = reinterpret_cast<const float4*>(si + row * QDIM) + lane;
        float4 r = *pr;
        float4 m = *pi;

        // Per-row reductions: A=<sr,p> B=<si,p> C=sum(sr) D=sum(si)
        float A = r.x * p4.x + r.y * p4.y + r.z * p4.z + r.w * p4.w;
        float B = m.x * p4.x + m.y * p4.y + m.z * p4.z + m.w * p4.w;
        float C = r.x + r.y + r.z + r.w;
        float D = m.x + m.y + m.z + m.w;
        #pragma unroll
        for (int o = 16; o > 0; o >>= 1) {
            A += __shfl_xor_sync(0xffffffffu, A, o);
            B += __shfl_xor_sync(0xffffffffu, B, o);
            C += __shfl_xor_sync(0xffffffffu, C, o);
            D += __shfl_xor_sync(0xffffffffu, D, o);
        }

        // out_real[j] = (A+D) p_j + sr[j] d_j - B
        // out_imag[j] = (B-C) p_j + si[j] d_j + A
        float cr = A + D;
        float ci = B - C;
        float4 outr, outi;
        outr.x = cr * p4.x + r.x * d4.x - B;
        outr.y = cr * p4.y + r.y * d4.y - B;
        outr.z = cr * p4.z + r.z * d4.z - B;
        outr.w = cr * p4.w + r.w * d4.w - B;
        outi.x = ci * p4.x + m.x * d4.x + A;
        outi.y = ci * p4.y + m.y * d4.y + A;
        outi.z = ci * p4.z + m.z * d4.z + A;
        outi.w = ci * p4.w + m.w * d4.w + A;

        reinterpret_cast<float4*>(out + row * QDIM)[lane]     = outr;
        reinterpret_cast<float4*>(out + N + row * QDIM)[lane] = outi;
    }
}

extern "C" void kernel_launch(void* const* d_in, const int* in_sizes, int n_in,
                              void* d_out, int out_size) {
    const float* sr     = (const float*)d_in[0];   // state_real [B,S,128]
    const float* si     = (const float*)d_in[1];   // state_imag [B,S,128]
    const float* params = (const float*)d_in[2];   // [128]
    float* out = (float*)d_out;                    // [2, B, S, 128]: real then imag

    int n_rows = in_sizes[0] / QDIM;

    int block = 256;
    int grid  = 148 * 8;   // grid-stride; ~8 blocks/SM resident
    qop_kernel<<<grid, block>>>(sr, si, params, out, n_rows);
}

// round 2
// speedup vs baseline: 1.0743x; 1.0743x over previous
#include <cuda_runtime.h>

#define QDIM 128

__global__ void __launch_bounds__(256) qop_kernel(
        const float* __restrict__ sr,
        const float* __restrict__ si,
        const float* __restrict__ params,
        float* __restrict__ out,
        int n_rows) {
    __shared__ float sp[QDIM];
    __shared__ float sd[QDIM];
    int tid = threadIdx.x;
    if (tid < QDIM) {
        float p = params[tid];
        sp[tid] = p;
        sd[tid] = 1.0f / (1.0f + expf(-p)) - p * p;   // sigmoid(p) - p^2
    }
    __syncthreads();

    int lane = tid & 31;
    float4 p4 = *reinterpret_cast<const float4*>(sp + lane * 4);
    float4 d4 = *reinterpret_cast<const float4*>(sd + lane * 4);

    long long N = (long long)n_rows * QDIM;   // elements per output tensor
    int warps_per_block = blockDim.x >> 5;
    long long w  = (long long)blockIdx.x * warps_per_block + (tid >> 5);
    long long nw = (long long)gridDim.x * warps_per_block;

    long long n_pairs = (long long)n_rows >> 1;   // rows processed in pairs

    for (long long pair = w; pair < n_pairs; pair += nw) {
        long long row0 = pair * 2;
        const float4* pr0 = reinterpret_cast<const float4*>(sr + row0 * QDIM) + lane;
        const float4* pi0 = reinterpret_cast<const float4*>(si + row0 * QDIM) + lane;

        // Batch all 4 loads up front: MLP=4 per warp iteration.
        float4 r0 = __ldcs(pr0);
        float4 r1 = __ldcs(pr0 + 32);
        float4 m0 = __ldcs(pi0);
        float4 m1 = __ldcs(pi0 + 32);

        // Per-row reductions (two independent chains → SHFL latency overlaps)
        float A0 = r0.x * p4.x + r0.y * p4.y + r0.z * p4.z + r0.w * p4.w;
        float B0 = m0.x * p4.x + m0.y * p4.y + m0.z * p4.z + m0.w * p4.w;
        float C0 = r0.x + r0.y + r0.z + r0.w;
        float D0 = m0.x + m0.y + m0.z + m0.w;
        float A1 = r1.x * p4.x + r1.y * p4.y + r1.z * p4.z + r1.w * p4.w;
        float B1 = m1.x * p4.x + m1.y * p4.y + m1.z * p4.z + m1.w * p4.w;
        float C1 = r1.x + r1.y + r1.z + r1.w;
        float D1 = m1.x + m1.y + m1.z + m1.w;
        #pragma unroll
        for (int o = 16; o > 0; o >>= 1) {
            A0 += __shfl_xor_sync(0xffffffffu, A0, o);
            A1 += __shfl_xor_sync(0xffffffffu, A1, o);
            B0 += __shfl_xor_sync(0xffffffffu, B0, o);
            B1 += __shfl_xor_sync(0xffffffffu, B1, o);
            C0 += __shfl_xor_sync(0xffffffffu, C0, o);
            C1 += __shfl_xor_sync(0xffffffffu, C1, o);
            D0 += __shfl_xor_sync(0xffffffffu, D0, o);
            D1 += __shfl_xor_sync(0xffffffffu, D1, o);
        }

        // out_real[j] = (A+D) p_j + sr[j] d_j - B
        // out_imag[j] = (B-C) p_j + si[j] d_j + A
        float cr0 = A0 + D0, ci0 = B0 - C0;
        float cr1 = A1 + D1, ci1 = B1 - C1;

        float4 o0, o1;
        o0.x = cr0 * p4.x + r0.x * d4.x - B0;
        o0.y = cr0 * p4.y + r0.y * d4.y - B0;
        o0.z = cr0 * p4.z + r0.z * d4.z - B0;
        o0.w = cr0 * p4.w + r0.w * d4.w - B0;
        o1.x = cr1 * p4.x + r1.x * d4.x - B1;
        o1.y = cr1 * p4.y + r1.y * d4.y - B1;
        o1.z = cr1 * p4.z + r1.z * d4.z - B1;
        o1.w = cr1 * p4.w + r1.w * d4.w - B1;
        float4* por = reinterpret_cast<float4*>(out + row0 * QDIM) + lane;
        __stcs(por,      o0);
        __stcs(por + 32, o1);

        o0.x = ci0 * p4.x + m0.x * d4.x + A0;
        o0.y = ci0 * p4.y + m0.y * d4.y + A0;
        o0.z = ci0 * p4.z + m0.z * d4.z + A0;
        o0.w = ci0 * p4.w + m0.w * d4.w + A0;
        o1.x = ci1 * p4.x + m1.x * d4.x + A1;
        o1.y = ci1 * p4.y + m1.y * d4.y + A1;
        o1.z = ci1 * p4.z + m1.z * d4.z + A1;
        o1.w = ci1 * p4.w + m1.w * d4.w + A1;
        float4* poi = reinterpret_cast<float4*>(out + N + row0 * QDIM) + lane;
        __stcs(poi,      o0);
        __stcs(poi + 32, o1);
    }

    // Tail: odd final row (not hit for this problem's shapes, but stay general)
    if ((n_rows & 1) && w == 0) {
        long long row = (long long)n_rows - 1;
        const float4* pr = reinterpret_cast<const float4*>(sr + row * QDIM) + lane;
        const float4* pi = reinterpret_cast<const float4*>(si + row * QDIM) + lane;
        float4 r = __ldcs(pr);
        float4 m = __ldcs(pi);
        float A = r.x * p4.x + r.y * p4.y + r.z * p4.z + r.w * p4.w;
        float B = m.x * p4.x + m.y * p4.y + m.z * p4.z + m.w * p4.w;
        float C = r.x + r.y + r.z + r.w;
        float D = m.x + m.y + m.z + m.w;
        #pragma unroll
        for (int o = 16; o > 0; o >>= 1) {
            A += __shfl_xor_sync(0xffffffffu, A, o);
            B += __shfl_xor_sync(0xffffffffu, B, o);
            C += __shfl_xor_sync(0xffffffffu, C, o);
            D += __shfl_xor_sync(0xffffffffu, D, o);
        }
        float cr = A + D, ci = B - C;
        float4 outr, outi;
        outr.x = cr * p4.x + r.x * d4.x - B;
        outr.y = cr * p4.y + r.y * d4.y - B;
        outr.z = cr * p4.z + r.z * d4.z - B;
        outr.w = cr * p4.w + r.w * d4.w - B;
        outi.x = ci * p4.x + m.x * d4.x + A;
        outi.y = ci * p4.y + m.y * d4.y + A;
        outi.z = ci * p4.z + m.z * d4.z + A;
        outi.w = ci * p4.w + m.w * d4.w + A;
        __stcs(reinterpret_cast<float4*>(out + row * QDIM) + lane,     outr);
        __stcs(reinterpret_cast<float4*>(out + N + row * QDIM) + lane, outi);
    }
}

extern "C" void kernel_launch(void* const* d_in, const int* in_sizes, int n_in,
                              void* d_out, int out_size) {
    const float* sr     = (const float*)d_in[0];   // state_real [B,S,128]
    const float* si     = (const float*)d_in[1];   // state_imag [B,S,128]
    const float* params = (const float*)d_in[2];   // [128]
    float* out = (float*)d_out;                    // [2, B, S, 128]: real then imag

    int n_rows = in_sizes[0] / QDIM;

    int block = 256;
    int grid  = 148 * 8;
    qop_kernel<<<grid, block>>>(sr, si, params, out, n_rows);
}